// round 3
// baseline (speedup 1.0000x reference)
#include <cuda_runtime.h>

// AttentionLayer: B=2, S=128, D=64, L=R=H=8
// q/k/v separated layout: [blr = b*64 + l*8 + r][row = s*8 + x_or_y][e]  (8192 floats per blr)

#define KPAD 68

__device__ float g_q[128 * 8192];
__device__ float g_k[128 * 8192];
__device__ float g_v[128 * 8192];
__device__ float g_m[256 * 4096];   // merged heads [b,s,64,64]

__device__ __forceinline__ float fast_ex2(float x) {
    float y; asm("ex2.approx.f32 %0, %1;" : "=f"(y) : "f"(x)); return y;
}

// ---------------------------------------------------------------------------
// Bilinear projection: P = (wl^T X wr + bias) * 0.125 per token, written into
// separated-head layout. grid (256 tokens, 3 projections), 256 threads.
// ---------------------------------------------------------------------------
__global__ __launch_bounds__(256) void qkv_proj_kernel(
    const float* __restrict__ qin, const float* __restrict__ kin, const float* __restrict__ vin,
    const float* __restrict__ wql, const float* __restrict__ wqr, const float* __restrict__ bq,
    const float* __restrict__ wkl, const float* __restrict__ wkr, const float* __restrict__ bk,
    const float* __restrict__ wvl, const float* __restrict__ wvr, const float* __restrict__ bv)
{
    __shared__ float sX[4096];
    __shared__ float sW[4096];
    __shared__ float sT[4096];
    const int token = blockIdx.x;
    const int proj  = blockIdx.y;
    const float *X, *wl, *wr, *bias;
    float* out;
    if (proj == 0)      { X = qin; wl = wql; wr = wqr; bias = bq; out = g_q; }
    else if (proj == 1) { X = kin; wl = wkl; wr = wkr; bias = bk; out = g_k; }
    else                { X = vin; wl = wvl; wr = wvr; bias = bv; out = g_v; }
    X += (size_t)token * 4096;

    const int t = threadIdx.x;
    for (int i = t; i < 4096; i += 256) { sX[i] = X[i]; sW[i] = wr[i]; }
    __syncthreads();

    const int r0 = (t >> 4) << 2;   // a / c tile base (0..60)
    const int d0 = (t & 15) << 2;   // d tile base   (0..60)

    // Phase 1: T = X @ wr
    float acc[4][4];
#pragma unroll
    for (int i = 0; i < 4; i++)
#pragma unroll
        for (int j = 0; j < 4; j++) acc[i][j] = 0.f;
    for (int b_ = 0; b_ < 64; b_++) {
        float xa[4], wd[4];
#pragma unroll
        for (int i = 0; i < 4; i++) xa[i] = sX[(r0 + i) * 64 + b_];
#pragma unroll
        for (int j = 0; j < 4; j++) wd[j] = sW[b_ * 64 + d0 + j];
#pragma unroll
        for (int i = 0; i < 4; i++)
#pragma unroll
            for (int j = 0; j < 4; j++) acc[i][j] += xa[i] * wd[j];
    }
#pragma unroll
    for (int i = 0; i < 4; i++)
#pragma unroll
        for (int j = 0; j < 4; j++) sT[(r0 + i) * 64 + d0 + j] = acc[i][j];
    __syncthreads();
    for (int i = t; i < 4096; i += 256) sW[i] = wl[i];
    __syncthreads();

    // Phase 2: P = wl^T @ T
#pragma unroll
    for (int i = 0; i < 4; i++)
#pragma unroll
        for (int j = 0; j < 4; j++) acc[i][j] = 0.f;
    for (int a = 0; a < 64; a++) {
        float la[4], td[4];
#pragma unroll
        for (int i = 0; i < 4; i++) la[i] = sW[a * 64 + r0 + i];
#pragma unroll
        for (int j = 0; j < 4; j++) td[j] = sT[a * 64 + d0 + j];
#pragma unroll
        for (int i = 0; i < 4; i++)
#pragma unroll
            for (int j = 0; j < 4; j++) acc[i][j] += la[i] * td[j];
    }

    const int b = token >> 7, s = token & 127;
#pragma unroll
    for (int i = 0; i < 4; i++) {
        const int c = r0 + i;
        const int l = c >> 3, x = c & 7;
#pragma unroll
        for (int j = 0; j < 4; j++) {
            const int d = d0 + j;
            const int r = d >> 3, e = d & 7;
            const float val = (acc[i][j] + bias[c * 64 + d]) * 0.125f;
            const int blr = (b << 6) + (l << 3) + r;
            out[(size_t)blr * 8192 + (s << 6) + (x << 3) + e] = val;
        }
    }
}

// ---------------------------------------------------------------------------
// Fused attention per (b,l,r). grid 256 (128 blr * 2 row-halves), 256 threads.
// Warp layout: lane = rw*4 + kq; lane owns row rw of an 8-row tile and the
// key subset k = kq + 4j (j=0..31). Softmax over k per (row,y) stripe.
// ---------------------------------------------------------------------------
__global__ __launch_bounds__(256) void attn_kernel()
{
    extern __shared__ float sm[];
    float* Ks = sm;
    float* Vs = sm + 128 * KPAD;

    const int bx   = blockIdx.x;
    const int blr  = bx >> 1;
    const int half = bx & 1;
    const float* gK = g_k + (size_t)blr * 8192;
    const float* gV = g_v + (size_t)blr * 8192;
    const float* gQ = g_q + (size_t)blr * 8192 + half * 4096;

    const int tid = threadIdx.x;
    for (int i = tid; i < 8192; i += 256) {
        const int kk = i >> 6, tt = i & 63;
        Ks[kk * KPAD + tt] = gK[i];
        Vs[kk * KPAD + tt] = gV[i];
    }
    __syncthreads();

    const int warp = tid >> 5, lane = tid & 31;
    const int rw = lane >> 2, kq = lane & 3;
    const int b = blr >> 6, l = (blr >> 3) & 7, r = blr & 7;
    const float CF = 0.125f * 1.4426950408889634f;  // fold sim/h and log2(e)

    for (int tile = 0; tile < 8; tile++) {
        const int lrow = warp * 64 + tile * 8 + rw;
        const float4 q0 = *(const float4*)(gQ + lrow * 8);
        const float4 q1 = *(const float4*)(gQ + lrow * 8 + 4);
        float qs[8] = { q0.x * CF, q0.y * CF, q0.z * CF, q0.w * CF,
                        q1.x * CF, q1.y * CF, q1.z * CF, q1.w * CF };
        float o[8];
#pragma unroll
        for (int e = 0; e < 8; e++) o[e] = 0.f;

        for (int y = 0; y < 8; y++) {
            float u[8];
#pragma unroll
            for (int e = 0; e < 8; e++) u[e] = 0.f;
            float ssum = 0.f;
            const float* kbase = Ks + kq * KPAD + y * 8;
            const float* vbase = Vs + kq * KPAD + y * 8;
#pragma unroll 8
            for (int j = 0; j < 32; j++) {
                const float* kr = kbase + j * (4 * KPAD);
                const float4 ka = *(const float4*)kr;
                const float4 kb = *(const float4*)(kr + 4);
                float sc = qs[0] * ka.x + qs[1] * ka.y + qs[2] * ka.z + qs[3] * ka.w
                         + qs[4] * kb.x + qs[5] * kb.y + qs[6] * kb.z + qs[7] * kb.w;
                const float ex = fast_ex2(sc);
                ssum += ex;
                const float* vr = vbase + j * (4 * KPAD);
                const float4 va = *(const float4*)vr;
                const float4 vb = *(const float4*)(vr + 4);
                u[0] += ex * va.x; u[1] += ex * va.y; u[2] += ex * va.z; u[3] += ex * va.w;
                u[4] += ex * vb.x; u[5] += ex * vb.y; u[6] += ex * vb.z; u[7] += ex * vb.w;
            }
            ssum += __shfl_xor_sync(0xffffffffu, ssum, 1);
            ssum += __shfl_xor_sync(0xffffffffu, ssum, 2);
            const float inv = 1.0f / ssum;
#pragma unroll
            for (int e = 0; e < 8; e++) o[e] += u[e] * inv;
        }

#pragma unroll
        for (int e = 0; e < 8; e++) {
            o[e] += __shfl_xor_sync(0xffffffffu, o[e], 1);
            o[e] += __shfl_xor_sync(0xffffffffu, o[e], 2);
        }
        if (kq == 0) {
            const int grow = half * 512 + lrow;
            const int s_ = grow >> 3, x = grow & 7;
            const int c = (l << 3) + x;
            float* dst = g_m + ((size_t)((b << 7) + s_) * 64 + c) * 64 + (r << 3);
            *(float4*)dst       = make_float4(o[0], o[1], o[2], o[3]);
            *(float4*)(dst + 4) = make_float4(o[4], o[5], o[6], o[7]);
        }
    }
}

// ---------------------------------------------------------------------------
// Output projection: out = (wo_l^T M wo_r + bo) * 0.125. grid 256, 256 thr.
// ---------------------------------------------------------------------------
__global__ __launch_bounds__(256) void out_proj_kernel(
    const float* __restrict__ wol, const float* __restrict__ wor,
    const float* __restrict__ bo, float* __restrict__ dout)
{
    __shared__ float sX[4096];
    __shared__ float sW[4096];
    __shared__ float sT[4096];
    const int token = blockIdx.x;
    const float* X = g_m + (size_t)token * 4096;
    const int t = threadIdx.x;
    for (int i = t; i < 4096; i += 256) { sX[i] = X[i]; sW[i] = wor[i]; }
    __syncthreads();

    const int r0 = (t >> 4) << 2;
    const int d0 = (t & 15) << 2;

    float acc[4][4];
#pragma unroll
    for (int i = 0; i < 4; i++)
#pragma unroll
        for (int j = 0; j < 4; j++) acc[i][j] = 0.f;
    for (int b_ = 0; b_ < 64; b_++) {
        float xa[4], wd[4];
#pragma unroll
        for (int i = 0; i < 4; i++) xa[i] = sX[(r0 + i) * 64 + b_];
#pragma unroll
        for (int j = 0; j < 4; j++) wd[j] = sW[b_ * 64 + d0 + j];
#pragma unroll
        for (int i = 0; i < 4; i++)
#pragma unroll
            for (int j = 0; j < 4; j++) acc[i][j] += xa[i] * wd[j];
    }
#pragma unroll
    for (int i = 0; i < 4; i++)
#pragma unroll
        for (int j = 0; j < 4; j++) sT[(r0 + i) * 64 + d0 + j] = acc[i][j];
    __syncthreads();
    for (int i = t; i < 4096; i += 256) sW[i] = wol[i];
    __syncthreads();

#pragma unroll
    for (int i = 0; i < 4; i++)
#pragma unroll
        for (int j = 0; j < 4; j++) acc[i][j] = 0.f;
    for (int a = 0; a < 64; a++) {
        float la[4], td[4];
#pragma unroll
        for (int i = 0; i < 4; i++) la[i] = sW[a * 64 + r0 + i];
#pragma unroll
        for (int j = 0; j < 4; j++) td[j] = sT[a * 64 + d0 + j];
#pragma unroll
        for (int i = 0; i < 4; i++)
#pragma unroll
            for (int j = 0; j < 4; j++) acc[i][j] += la[i] * td[j];
    }

#pragma unroll
    for (int i = 0; i < 4; i++) {
        const int c = r0 + i;
#pragma unroll
        for (int j = 0; j < 4; j++) {
            const int d = d0 + j;
            dout[(size_t)token * 4096 + c * 64 + d] =
                (acc[i][j] + bo[c * 64 + d]) * 0.125f;
        }
    }
}

// ---------------------------------------------------------------------------
extern "C" void kernel_launch(void* const* d_in, const int* in_sizes, int n_in,
                              void* d_out, int out_size)
{
    const float* qin = (const float*)d_in[0];
    const float* kin = (const float*)d_in[1];
    const float* vin = (const float*)d_in[2];
    const float* wql = (const float*)d_in[3];
    const float* wqr = (const float*)d_in[4];
    const float* bq  = (const float*)d_in[5];
    const float* wkl = (const float*)d_in[6];
    const float* wkr = (const float*)d_in[7];
    const float* bk  = (const float*)d_in[8];
    const float* wvl = (const float*)d_in[9];
    const float* wvr = (const float*)d_in[10];
    const float* bv  = (const float*)d_in[11];
    const float* wol = (const float*)d_in[12];
    const float* wor = (const float*)d_in[13];
    const float* bo  = (const float*)d_in[14];
    float* dout = (float*)d_out;

    const int smem_attn = 2 * 128 * KPAD * (int)sizeof(float);  // 69632 B
    cudaFuncSetAttribute(attn_kernel, cudaFuncAttributeMaxDynamicSharedMemorySize, smem_attn);

    qkv_proj_kernel<<<dim3(256, 3), 256>>>(qin, kin, vin,
                                           wql, wqr, bq,
                                           wkl, wkr, bk,
                                           wvl, wvr, bv);
    attn_kernel<<<256, 256, smem_attn>>>();
    out_proj_kernel<<<256, 256>>>(wol, wor, bo, dout);
}

// round 6
// speedup vs baseline: 1.0267x; 1.0267x over previous
#include <cuda_runtime.h>

// AttentionLayer: B=2, S=128, D=64, L=R=H=8
// q/k/v separated layout: [blr = b*64 + l*8 + r][row = s*8 + x_or_y][e]  (8192 floats per blr)

#define KPAD 68

__device__ float g_q[128 * 8192];
__device__ float g_k[128 * 8192];
__device__ float g_v[128 * 8192];
__device__ float g_m[256 * 4096];   // merged heads [b,s,64,64]

typedef unsigned long long u64;

__device__ __forceinline__ float fast_ex2(float x) {
    float y; asm("ex2.approx.f32 %0, %1;" : "=f"(y) : "f"(x)); return y;
}
__device__ __forceinline__ u64 pack2(float lo, float hi) {
    u64 r; asm("mov.b64 %0, {%1, %2};" : "=l"(r) : "f"(lo), "f"(hi)); return r;
}
__device__ __forceinline__ void unpack2(u64 v, float& lo, float& hi) {
    asm("mov.b64 {%0, %1}, %2;" : "=f"(lo), "=f"(hi) : "l"(v));
}
__device__ __forceinline__ u64 fma2(u64 a, u64 b, u64 c) {
    u64 d; asm("fma.rn.f32x2 %0, %1, %2, %3;" : "=l"(d) : "l"(a), "l"(b), "l"(c)); return d;
}
__device__ __forceinline__ u64 mul2(u64 a, u64 b) {
    u64 d; asm("mul.rn.f32x2 %0, %1, %2;" : "=l"(d) : "l"(a), "l"(b)); return d;
}

// ---------------------------------------------------------------------------
// Bilinear projection: P = (wl^T X wr + bias) * 0.125 per token, written into
// separated-head layout. grid (256 tokens, 3 projections), 256 threads.
// X staged transposed (pad 68) so the a-strided operand is one LDS.128.
// ---------------------------------------------------------------------------
__global__ __launch_bounds__(256) void qkv_proj_kernel(
    const float* __restrict__ qin, const float* __restrict__ kin, const float* __restrict__ vin,
    const float* __restrict__ wql, const float* __restrict__ wqr, const float* __restrict__ bq,
    const float* __restrict__ wkl, const float* __restrict__ wkr, const float* __restrict__ bk,
    const float* __restrict__ wvl, const float* __restrict__ wvr, const float* __restrict__ bv)
{
    __shared__ float sXT[64 * 68];   // X transposed [b*68 + a]; reused as T [a*64 + d]
    __shared__ float sW[4096];
    float* sT = sXT;

    const int token = blockIdx.x;
    const int proj  = blockIdx.y;
    const float *X, *wl, *wr, *bias;
    float* out;
    if (proj == 0)      { X = qin; wl = wql; wr = wqr; bias = bq; out = g_q; }
    else if (proj == 1) { X = kin; wl = wkl; wr = wkr; bias = bk; out = g_k; }
    else                { X = vin; wl = wvl; wr = wvr; bias = bv; out = g_v; }
    X += (size_t)token * 4096;

    const int t = threadIdx.x;
    for (int i = t; i < 4096; i += 256) {
        const int a = i >> 6, bb = i & 63;
        sXT[bb * 68 + a] = X[i];
        sW[i] = wr[i];
    }
    __syncthreads();

    const int r0 = (t >> 4) << 2;   // c/a tile base (0..60)
    const int d0 = (t & 15) << 2;   // d tile base   (0..60)

    // Phase 1: T = X @ wr   (T[a,d] = sum_b X[a,b] wr[b,d])
    u64 acc[4][2];
#pragma unroll
    for (int i = 0; i < 4; i++) { acc[i][0] = 0ull; acc[i][1] = 0ull; }
    for (int bb = 0; bb < 64; bb++) {
        const float4 xa = *(const float4*)&sXT[bb * 68 + r0];
        const ulonglong2 w = *(const ulonglong2*)&sW[bb * 64 + d0];
        const u64 xp0 = pack2(xa.x, xa.x), xp1 = pack2(xa.y, xa.y);
        const u64 xp2 = pack2(xa.z, xa.z), xp3 = pack2(xa.w, xa.w);
        acc[0][0] = fma2(xp0, w.x, acc[0][0]); acc[0][1] = fma2(xp0, w.y, acc[0][1]);
        acc[1][0] = fma2(xp1, w.x, acc[1][0]); acc[1][1] = fma2(xp1, w.y, acc[1][1]);
        acc[2][0] = fma2(xp2, w.x, acc[2][0]); acc[2][1] = fma2(xp2, w.y, acc[2][1]);
        acc[3][0] = fma2(xp3, w.x, acc[3][0]); acc[3][1] = fma2(xp3, w.y, acc[3][1]);
    }
    __syncthreads();  // all sXT reads done before overwrite with T
#pragma unroll
    for (int i = 0; i < 4; i++)
        *(ulonglong2*)&sT[(r0 + i) * 64 + d0] = make_ulonglong2(acc[i][0], acc[i][1]);
    for (int i = t; i < 4096; i += 256) sW[i] = wl[i];
    __syncthreads();

    // Phase 2: P = wl^T @ T  (P[c,d] = sum_a wl[a,c] T[a,d])
#pragma unroll
    for (int i = 0; i < 4; i++) { acc[i][0] = 0ull; acc[i][1] = 0ull; }
    for (int a = 0; a < 64; a++) {
        const float4 la = *(const float4*)&sW[a * 64 + r0];
        const ulonglong2 td = *(const ulonglong2*)&sT[a * 64 + d0];
        const u64 lp0 = pack2(la.x, la.x), lp1 = pack2(la.y, la.y);
        const u64 lp2 = pack2(la.z, la.z), lp3 = pack2(la.w, la.w);
        acc[0][0] = fma2(lp0, td.x, acc[0][0]); acc[0][1] = fma2(lp0, td.y, acc[0][1]);
        acc[1][0] = fma2(lp1, td.x, acc[1][0]); acc[1][1] = fma2(lp1, td.y, acc[1][1]);
        acc[2][0] = fma2(lp2, td.x, acc[2][0]); acc[2][1] = fma2(lp2, td.y, acc[2][1]);
        acc[3][0] = fma2(lp3, td.x, acc[3][0]); acc[3][1] = fma2(lp3, td.y, acc[3][1]);
    }

    const int b = token >> 7, s = token & 127;
    const int r = d0 >> 3, e0 = d0 & 7;   // 4 consecutive d never cross an 8-boundary
#pragma unroll
    for (int i = 0; i < 4; i++) {
        const int c = r0 + i;
        const int l = c >> 3, x = c & 7;
        const float4 bi = *(const float4*)&bias[c * 64 + d0];
        float v0, v1, v2, v3;
        unpack2(acc[i][0], v0, v1);
        unpack2(acc[i][1], v2, v3);
        const int blr = (b << 6) + (l << 3) + r;
        float4 res = make_float4((v0 + bi.x) * 0.125f, (v1 + bi.y) * 0.125f,
                                 (v2 + bi.z) * 0.125f, (v3 + bi.w) * 0.125f);
        *(float4*)&out[(size_t)blr * 8192 + (s << 6) + (x << 3) + e0] = res;
    }
}

// ---------------------------------------------------------------------------
// Fused attention per (b,l,r). grid 256 (128 blr * 2 row-halves), 256 threads.
// Warp layout: lane = rw*4 + kq; lane owns row rw of an 8-row tile and the
// key subset k = kq + 4j (j=0..31). Softmax over k per (row,y) stripe.
// All MACs via packed fma.rn.f32x2.
// ---------------------------------------------------------------------------
__global__ __launch_bounds__(256) void attn_kernel()
{
    extern __shared__ float sm[];
    float* Ks = sm;
    float* Vs = sm + 128 * KPAD;

    const int bx   = blockIdx.x;
    const int blr  = bx >> 1;
    const int half = bx & 1;
    const float* gK = g_k + (size_t)blr * 8192;
    const float* gV = g_v + (size_t)blr * 8192;
    const float* gQ = g_q + (size_t)blr * 8192 + half * 4096;

    const int tid = threadIdx.x;
    for (int i = tid; i < 8192; i += 256) {
        const int kk = i >> 6, tt = i & 63;
        Ks[kk * KPAD + tt] = gK[i];
        Vs[kk * KPAD + tt] = gV[i];
    }
    __syncthreads();

    const int warp = tid >> 5, lane = tid & 31;
    const int rw = lane >> 2, kq = lane & 3;
    const int b = blr >> 6, l = (blr >> 3) & 7, r = blr & 7;
    const float CF = 0.125f * 1.4426950408889634f;  // fold sim/h and log2(e)

    for (int tile = 0; tile < 8; tile++) {
        const int lrow = warp * 64 + tile * 8 + rw;
        const float4 q0 = *(const float4*)(gQ + lrow * 8);
        const float4 q1 = *(const float4*)(gQ + lrow * 8 + 4);
        const u64 qp0 = pack2(q0.x * CF, q0.y * CF);
        const u64 qp1 = pack2(q0.z * CF, q0.w * CF);
        const u64 qp2 = pack2(q1.x * CF, q1.y * CF);
        const u64 qp3 = pack2(q1.z * CF, q1.w * CF);

        u64 o2[4] = {0ull, 0ull, 0ull, 0ull};

        for (int y = 0; y < 8; y++) {
            u64 u2[4] = {0ull, 0ull, 0ull, 0ull};
            float ssum = 0.f;
            const float* kb = Ks + kq * KPAD + y * 8;
            const float* vb = Vs + kq * KPAD + y * 8;
#pragma unroll 8
            for (int j = 0; j < 32; j++) {
                const ulonglong2* kr = (const ulonglong2*)(kb + j * (4 * KPAD));
                const ulonglong2 kA = kr[0];
                const ulonglong2 kB = kr[1];
                const u64 accp = fma2(qp0, kA.x,
                                 fma2(qp1, kA.y,
                                 fma2(qp2, kB.x,
                                 mul2(qp3, kB.y))));
                float slo, shi;
                unpack2(accp, slo, shi);
                const float ex = fast_ex2(slo + shi);
                ssum += ex;
                const u64 ee = pack2(ex, ex);
                const ulonglong2* vr = (const ulonglong2*)(vb + j * (4 * KPAD));
                const ulonglong2 vA = vr[0];
                const ulonglong2 vB = vr[1];
                u2[0] = fma2(ee, vA.x, u2[0]);
                u2[1] = fma2(ee, vA.y, u2[1]);
                u2[2] = fma2(ee, vB.x, u2[2]);
                u2[3] = fma2(ee, vB.y, u2[3]);
            }
            ssum += __shfl_xor_sync(0xffffffffu, ssum, 1);
            ssum += __shfl_xor_sync(0xffffffffu, ssum, 2);
            const float inv = 1.0f / ssum;
            const u64 iv = pack2(inv, inv);
            o2[0] = fma2(iv, u2[0], o2[0]);
            o2[1] = fma2(iv, u2[1], o2[1]);
            o2[2] = fma2(iv, u2[2], o2[2]);
            o2[3] = fma2(iv, u2[3], o2[3]);
        }

        float o[8];
        unpack2(o2[0], o[0], o[1]);
        unpack2(o2[1], o[2], o[3]);
        unpack2(o2[2], o[4], o[5]);
        unpack2(o2[3], o[6], o[7]);
#pragma unroll
        for (int e = 0; e < 8; e++) {
            o[e] += __shfl_xor_sync(0xffffffffu, o[e], 1);
            o[e] += __shfl_xor_sync(0xffffffffu, o[e], 2);
        }
        if (kq == 0) {
            const int grow = half * 512 + lrow;
            const int s_ = grow >> 3, x = grow & 7;
            const int c = (l << 3) + x;
            float* dst = g_m + ((size_t)((b << 7) + s_) * 64 + c) * 64 + (r << 3);
            *(float4*)dst       = make_float4(o[0], o[1], o[2], o[3]);
            *(float4*)(dst + 4) = make_float4(o[4], o[5], o[6], o[7]);
        }
    }
}

// ---------------------------------------------------------------------------
// Output projection: out = (wo_l^T M wo_r + bo) * 0.125. grid 256, 256 thr.
// ---------------------------------------------------------------------------
__global__ __launch_bounds__(256) void out_proj_kernel(
    const float* __restrict__ wol, const float* __restrict__ wor,
    const float* __restrict__ bo, float* __restrict__ dout)
{
    __shared__ float sXT[64 * 68];
    __shared__ float sW[4096];
    float* sT = sXT;

    const int token = blockIdx.x;
    const float* X = g_m + (size_t)token * 4096;
    const int t = threadIdx.x;
    for (int i = t; i < 4096; i += 256) {
        const int a = i >> 6, bb = i & 63;
        sXT[bb * 68 + a] = X[i];
        sW[i] = wor[i];
    }
    __syncthreads();

    const int r0 = (t >> 4) << 2;
    const int d0 = (t & 15) << 2;

    u64 acc[4][2];
#pragma unroll
    for (int i = 0; i < 4; i++) { acc[i][0] = 0ull; acc[i][1] = 0ull; }
    for (int bb = 0; bb < 64; bb++) {
        const float4 xa = *(const float4*)&sXT[bb * 68 + r0];
        const ulonglong2 w = *(const ulonglong2*)&sW[bb * 64 + d0];
        const u64 xp0 = pack2(xa.x, xa.x), xp1 = pack2(xa.y, xa.y);
        const u64 xp2 = pack2(xa.z, xa.z), xp3 = pack2(xa.w, xa.w);
        acc[0][0] = fma2(xp0, w.x, acc[0][0]); acc[0][1] = fma2(xp0, w.y, acc[0][1]);
        acc[1][0] = fma2(xp1, w.x, acc[1][0]); acc[1][1] = fma2(xp1, w.y, acc[1][1]);
        acc[2][0] = fma2(xp2, w.x, acc[2][0]); acc[2][1] = fma2(xp2, w.y, acc[2][1]);
        acc[3][0] = fma2(xp3, w.x, acc[3][0]); acc[3][1] = fma2(xp3, w.y, acc[3][1]);
    }
    __syncthreads();
#pragma unroll
    for (int i = 0; i < 4; i++)
        *(ulonglong2*)&sT[(r0 + i) * 64 + d0] = make_ulonglong2(acc[i][0], acc[i][1]);
    for (int i = t; i < 4096; i += 256) sW[i] = wol[i];
    __syncthreads();

#pragma unroll
    for (int i = 0; i < 4; i++) { acc[i][0] = 0ull; acc[i][1] = 0ull; }
    for (int a = 0; a < 64; a++) {
        const float4 la = *(const float4*)&sW[a * 64 + r0];
        const ulonglong2 td = *(const ulonglong2*)&sT[a * 64 + d0];
        const u64 lp0 = pack2(la.x, la.x), lp1 = pack2(la.y, la.y);
        const u64 lp2 = pack2(la.z, la.z), lp3 = pack2(la.w, la.w);
        acc[0][0] = fma2(lp0, td.x, acc[0][0]); acc[0][1] = fma2(lp0, td.y, acc[0][1]);
        acc[1][0] = fma2(lp1, td.x, acc[1][0]); acc[1][1] = fma2(lp1, td.y, acc[1][1]);
        acc[2][0] = fma2(lp2, td.x, acc[2][0]); acc[2][1] = fma2(lp2, td.y, acc[2][1]);
        acc[3][0] = fma2(lp3, td.x, acc[3][0]); acc[3][1] = fma2(lp3, td.y, acc[3][1]);
    }

#pragma unroll
    for (int i = 0; i < 4; i++) {
        const int c = r0 + i;
        const float4 bi = *(const float4*)&bo[c * 64 + d0];
        float v0, v1, v2, v3;
        unpack2(acc[i][0], v0, v1);
        unpack2(acc[i][1], v2, v3);
        float4 res = make_float4((v0 + bi.x) * 0.125f, (v1 + bi.y) * 0.125f,
                                 (v2 + bi.z) * 0.125f, (v3 + bi.w) * 0.125f);
        *(float4*)&dout[(size_t)token * 4096 + c * 64 + d0] = res;
    }
}

// ---------------------------------------------------------------------------
extern "C" void kernel_launch(void* const* d_in, const int* in_sizes, int n_in,
                              void* d_out, int out_size)
{
    const float* qin = (const float*)d_in[0];
    const float* kin = (const float*)d_in[1];
    const float* vin = (const float*)d_in[2];
    const float* wql = (const float*)d_in[3];
    const float* wqr = (const float*)d_in[4];
    const float* bq  = (const float*)d_in[5];
    const float* wkl = (const float*)d_in[6];
    const float* wkr = (const float*)d_in[7];
    const float* bk  = (const float*)d_in[8];
    const float* wvl = (const float*)d_in[9];
    const float* wvr = (const float*)d_in[10];
    const float* bv  = (const float*)d_in[11];
    const float* wol = (const float*)d_in[12];
    const float* wor = (const float*)d_in[13];
    const float* bo  = (const float*)d_in[14];
    float* dout = (float*)d_out;

    const int smem_attn = 2 * 128 * KPAD * (int)sizeof(float);  // 69632 B
    cudaFuncSetAttribute(attn_kernel, cudaFuncAttributeMaxDynamicSharedMemorySize, smem_attn);

    qkv_proj_kernel<<<dim3(256, 3), 256>>>(qin, kin, vin,
                                           wql, wqr, bq,
                                           wkl, wkr, bk,
                                           wvl, wvr, bv);
    attn_kernel<<<256, 256, smem_attn>>>();
    out_proj_kernel<<<256, 256>>>(wol, wor, bo, dout);
}

// round 8
// speedup vs baseline: 2.7768x; 2.7046x over previous
#include <cuda_runtime.h>

// AttentionLayer: B=2, S=128, D=64, L=R=H=8
// q/k/v separated layout: [blr = b*64 + l*8 + r][row = s*8 + x_or_y][e]  (8192 floats per blr)

__device__ float g_q[128 * 8192];
__device__ float g_k[128 * 8192];
__device__ float g_v[128 * 8192];
__device__ float g_m[256 * 4096];   // merged heads [b,s,64,64]

typedef unsigned long long u64;

__device__ __forceinline__ float fast_ex2(float x) {
    float y; asm("ex2.approx.f32 %0, %1;" : "=f"(y) : "f"(x)); return y;
}
__device__ __forceinline__ float rcp_fast(float x) {
    float y; asm("rcp.approx.f32 %0, %1;" : "=f"(y) : "f"(x)); return y;
}
__device__ __forceinline__ unsigned cvt_tf32(float x) {
    unsigned r; asm("cvt.rna.tf32.f32 %0, %1;" : "=r"(r) : "f"(x)); return r;
}
__device__ __forceinline__ void mma_tf32(
    float& d0, float& d1, float& d2, float& d3,
    unsigned a0, unsigned a1, unsigned a2, unsigned a3,
    unsigned b0, unsigned b1,
    float c0, float c1, float c2, float c3)
{
    asm("mma.sync.aligned.m16n8k8.row.col.f32.tf32.tf32.f32 "
        "{%0,%1,%2,%3},{%4,%5,%6,%7},{%8,%9},{%10,%11,%12,%13};"
        : "=f"(d0), "=f"(d1), "=f"(d2), "=f"(d3)
        : "r"(a0), "r"(a1), "r"(a2), "r"(a3), "r"(b0), "r"(b1),
          "f"(c0), "f"(c1), "f"(c2), "f"(c3));
}
__device__ __forceinline__ u64 pack2(float lo, float hi) {
    u64 r; asm("mov.b64 %0, {%1, %2};" : "=l"(r) : "f"(lo), "f"(hi)); return r;
}
__device__ __forceinline__ void unpack2(u64 v, float& lo, float& hi) {
    asm("mov.b64 {%0, %1}, %2;" : "=f"(lo), "=f"(hi) : "l"(v));
}
__device__ __forceinline__ u64 fma2(u64 a, u64 b, u64 c) {
    u64 d; asm("fma.rn.f32x2 %0, %1, %2, %3;" : "=l"(d) : "l"(a), "l"(b), "l"(c)); return d;
}

// ---------------------------------------------------------------------------
// Bilinear projection: P = (wl^T X wr + bias) * 0.125 per token, written into
// separated-head layout. grid (256 tokens, 3 projections), 256 threads.
// ---------------------------------------------------------------------------
__global__ __launch_bounds__(256) void qkv_proj_kernel(
    const float* __restrict__ qin, const float* __restrict__ kin, const float* __restrict__ vin,
    const float* __restrict__ wql, const float* __restrict__ wqr, const float* __restrict__ bq,
    const float* __restrict__ wkl, const float* __restrict__ wkr, const float* __restrict__ bk,
    const float* __restrict__ wvl, const float* __restrict__ wvr, const float* __restrict__ bv)
{
    __shared__ float sXT[64 * 68];   // X transposed [b*68 + a]; reused as T [a*64 + d]
    __shared__ float sW[4096];
    float* sT = sXT;

    const int token = blockIdx.x;
    const int proj  = blockIdx.y;
    const float *X, *wl, *wr, *bias;
    float* out;
    if (proj == 0)      { X = qin; wl = wql; wr = wqr; bias = bq; out = g_q; }
    else if (proj == 1) { X = kin; wl = wkl; wr = wkr; bias = bk; out = g_k; }
    else                { X = vin; wl = wvl; wr = wvr; bias = bv; out = g_v; }
    X += (size_t)token * 4096;

    const int t = threadIdx.x;
    for (int i = t; i < 4096; i += 256) {
        const int a = i >> 6, bb = i & 63;
        sXT[bb * 68 + a] = X[i];
        sW[i] = wr[i];
    }
    __syncthreads();

    const int r0 = (t >> 4) << 2;   // c/a tile base (0..60)
    const int d0 = (t & 15) << 2;   // d tile base   (0..60)

    // Phase 1: T = X @ wr
    u64 acc[4][2];
#pragma unroll
    for (int i = 0; i < 4; i++) { acc[i][0] = 0ull; acc[i][1] = 0ull; }
    for (int bb = 0; bb < 64; bb++) {
        const float4 xa = *(const float4*)&sXT[bb * 68 + r0];
        const ulonglong2 w = *(const ulonglong2*)&sW[bb * 64 + d0];
        const u64 xp0 = pack2(xa.x, xa.x), xp1 = pack2(xa.y, xa.y);
        const u64 xp2 = pack2(xa.z, xa.z), xp3 = pack2(xa.w, xa.w);
        acc[0][0] = fma2(xp0, w.x, acc[0][0]); acc[0][1] = fma2(xp0, w.y, acc[0][1]);
        acc[1][0] = fma2(xp1, w.x, acc[1][0]); acc[1][1] = fma2(xp1, w.y, acc[1][1]);
        acc[2][0] = fma2(xp2, w.x, acc[2][0]); acc[2][1] = fma2(xp2, w.y, acc[2][1]);
        acc[3][0] = fma2(xp3, w.x, acc[3][0]); acc[3][1] = fma2(xp3, w.y, acc[3][1]);
    }
    __syncthreads();
#pragma unroll
    for (int i = 0; i < 4; i++)
        *(ulonglong2*)&sT[(r0 + i) * 64 + d0] = make_ulonglong2(acc[i][0], acc[i][1]);
    for (int i = t; i < 4096; i += 256) sW[i] = wl[i];
    __syncthreads();

    // Phase 2: P = wl^T @ T
#pragma unroll
    for (int i = 0; i < 4; i++) { acc[i][0] = 0ull; acc[i][1] = 0ull; }
    for (int a = 0; a < 64; a++) {
        const float4 la = *(const float4*)&sW[a * 64 + r0];
        const ulonglong2 td = *(const ulonglong2*)&sT[a * 64 + d0];
        const u64 lp0 = pack2(la.x, la.x), lp1 = pack2(la.y, la.y);
        const u64 lp2 = pack2(la.z, la.z), lp3 = pack2(la.w, la.w);
        acc[0][0] = fma2(lp0, td.x, acc[0][0]); acc[0][1] = fma2(lp0, td.y, acc[0][1]);
        acc[1][0] = fma2(lp1, td.x, acc[1][0]); acc[1][1] = fma2(lp1, td.y, acc[1][1]);
        acc[2][0] = fma2(lp2, td.x, acc[2][0]); acc[2][1] = fma2(lp2, td.y, acc[2][1]);
        acc[3][0] = fma2(lp3, td.x, acc[3][0]); acc[3][1] = fma2(lp3, td.y, acc[3][1]);
    }

    const int b = token >> 7, s = token & 127;
    const int r = d0 >> 3, e0 = d0 & 7;
#pragma unroll
    for (int i = 0; i < 4; i++) {
        const int c = r0 + i;
        const int l = c >> 3, x = c & 7;
        const float4 bi = *(const float4*)&bias[c * 64 + d0];
        float v0, v1, v2, v3;
        unpack2(acc[i][0], v0, v1);
        unpack2(acc[i][1], v2, v3);
        const int blr = (b << 6) + (l << 3) + r;
        float4 res = make_float4((v0 + bi.x) * 0.125f, (v1 + bi.y) * 0.125f,
                                 (v2 + bi.z) * 0.125f, (v3 + bi.w) * 0.125f);
        *(float4*)&out[(size_t)blr * 8192 + (s << 6) + (x << 3) + e0] = res;
    }
}

// ---------------------------------------------------------------------------
// Tensor-core attention per (b,l,r,half). grid 256, 8 warps.
// Warp owns 4 m16 row-tiles. Per (tile, y): 16 key-chunks of 8; per chunk:
//   S-tile = Q(16x8,tf32) @ K-chunk^T via mma.m16n8k8 (B cols key-permuted so
//   the exp'd C-fragment is directly the A-fragment of the AV mma),
//   exp via ex2 (CF folded into Q), per-row sums thread-local,
//   O_y += P @ V-chunk via second mma. Normalize per y after chunk loop.
// K staged in smem as tf32 [y][e][s pad132]; V as tf32 [y][s][e]. Both
// fragment load patterns are bank-conflict-free.
// ---------------------------------------------------------------------------
__global__ __launch_bounds__(256) void attn_kernel()
{
    extern __shared__ unsigned smu[];
    unsigned* Ku = smu;            // 8*8*132 = 8448
    unsigned* Vu = smu + 8448;     // 8*128*8 = 8192

    const int bx   = blockIdx.x;
    const int blr  = bx >> 1;
    const int half = bx & 1;
    const float* gK = g_k + (size_t)blr * 8192;
    const float* gV = g_v + (size_t)blr * 8192;
    const float* gQ = g_q + (size_t)blr * 8192 + half * 4096;

    const int tid = threadIdx.x;
    for (int i4 = tid; i4 < 2048; i4 += 256) {
        const float4 kv = ((const float4*)gK)[i4];
        const float4 vv = ((const float4*)gV)[i4];
        const int idx = i4 << 2;
        const int s = idx >> 6, y = (idx >> 3) & 7, e0 = idx & 7;  // e0 in {0,4}
        unsigned* kd = Ku + (y * 8 + e0) * 132 + s;
        kd[0]   = cvt_tf32(kv.x);
        kd[132] = cvt_tf32(kv.y);
        kd[264] = cvt_tf32(kv.z);
        kd[396] = cvt_tf32(kv.w);
        *(uint4*)(Vu + y * 1024 + s * 8 + e0) =
            make_uint4(cvt_tf32(vv.x), cvt_tf32(vv.y), cvt_tf32(vv.z), cvt_tf32(vv.w));
    }
    __syncthreads();

    const int lane = tid & 31, warp = tid >> 5;
    const int g  = lane >> 2;          // group id (row / B col n)
    const int q4 = lane & 3;           // thread in group
    const int pk = ((g & 1) << 2) | (g >> 1);  // permuted key offset for S-mma B
    const int b = blr >> 6, l = (blr >> 3) & 7, r = blr & 7;
    const float CF = 0.125f * 1.4426950408889634f;  // sim/h fold + log2(e)

    const unsigned* Kp = Ku + q4 * 132 + pk;   // + y*1056 + sc*8 ; b1 at +528
    const unsigned* Vp = Vu + q4 * 8 + g;      // + y*1024 + sc*64; b1 at +32

    for (int tile = 0; tile < 4; tile++) {
        const int row0 = warp * 64 + tile * 16;
        const int qrow = row0 + g;
        const unsigned qa0 = cvt_tf32(gQ[qrow * 8 + q4] * CF);
        const unsigned qa1 = cvt_tf32(gQ[(qrow + 8) * 8 + q4] * CF);
        const unsigned qa2 = cvt_tf32(gQ[qrow * 8 + q4 + 4] * CF);
        const unsigned qa3 = cvt_tf32(gQ[(qrow + 8) * 8 + q4 + 4] * CF);

        float O0 = 0.f, O1 = 0.f, O2 = 0.f, O3 = 0.f;

        for (int y = 0; y < 8; y++) {
            const unsigned* kp = Kp + y * 1056;
            const unsigned* vp = Vp + y * 1024;
            float oa0 = 0.f, oa1 = 0.f, oa2 = 0.f, oa3 = 0.f;
            float ob0 = 0.f, ob1 = 0.f, ob2 = 0.f, ob3 = 0.f;
            float ss0 = 0.f, ss1 = 0.f;
#pragma unroll 4
            for (int sc = 0; sc < 16; sc++) {
                const unsigned kb0 = kp[sc * 8];
                const unsigned kb1 = kp[sc * 8 + 528];
                float s0, s1, s2, s3;
                mma_tf32(s0, s1, s2, s3, qa0, qa1, qa2, qa3, kb0, kb1,
                         0.f, 0.f, 0.f, 0.f);
                // exp2 (scores pre-scaled via Q), truncate to tf32 so ssum and
                // the AV mma see identical weights (bias cancels on normalize)
                const unsigned t0 = __float_as_uint(fast_ex2(s0)) & 0xFFFFE000u;
                const unsigned t1 = __float_as_uint(fast_ex2(s1)) & 0xFFFFE000u;
                const unsigned t2 = __float_as_uint(fast_ex2(s2)) & 0xFFFFE000u;
                const unsigned t3 = __float_as_uint(fast_ex2(s3)) & 0xFFFFE000u;
                ss0 += __uint_as_float(t0) + __uint_as_float(t1);
                ss1 += __uint_as_float(t2) + __uint_as_float(t3);
                const unsigned vb0 = vp[sc * 64];
                const unsigned vb1 = vp[sc * 64 + 32];
                // A-frag = {t0, t2, t1, t3} thanks to the key permutation
                if (sc & 1)
                    mma_tf32(ob0, ob1, ob2, ob3, t0, t2, t1, t3, vb0, vb1,
                             ob0, ob1, ob2, ob3);
                else
                    mma_tf32(oa0, oa1, oa2, oa3, t0, t2, t1, t3, vb0, vb1,
                             oa0, oa1, oa2, oa3);
            }
            oa0 += ob0; oa1 += ob1; oa2 += ob2; oa3 += ob3;
            ss0 += __shfl_xor_sync(0xffffffffu, ss0, 1);
            ss0 += __shfl_xor_sync(0xffffffffu, ss0, 2);
            ss1 += __shfl_xor_sync(0xffffffffu, ss1, 1);
            ss1 += __shfl_xor_sync(0xffffffffu, ss1, 2);
            const float inv0 = rcp_fast(ss0);
            const float inv1 = rcp_fast(ss1);
            O0 = fmaf(oa0, inv0, O0);
            O1 = fmaf(oa1, inv0, O1);
            O2 = fmaf(oa2, inv1, O2);
            O3 = fmaf(oa3, inv1, O3);
        }

        const int grow = half * 512 + row0 + g;
        const int s_ = grow >> 3, x = grow & 7;
        const int c = (l << 3) + x;
        float* dst = g_m + ((size_t)((b << 7) + s_) * 64 + c) * 64 + (r << 3) + 2 * q4;
        *(float2*)dst = make_float2(O0, O1);
        *(float2*)(dst + 4096) = make_float2(O2, O3);   // row+8 -> s+1, same x
    }
}

// ---------------------------------------------------------------------------
// Output projection: out = (wo_l^T M wo_r + bo) * 0.125. grid 256, 256 thr.
// ---------------------------------------------------------------------------
__global__ __launch_bounds__(256) void out_proj_kernel(
    const float* __restrict__ wol, const float* __restrict__ wor,
    const float* __restrict__ bo, float* __restrict__ dout)
{
    __shared__ float sXT[64 * 68];
    __shared__ float sW[4096];
    float* sT = sXT;

    const int token = blockIdx.x;
    const float* X = g_m + (size_t)token * 4096;
    const int t = threadIdx.x;
    for (int i = t; i < 4096; i += 256) {
        const int a = i >> 6, bb = i & 63;
        sXT[bb * 68 + a] = X[i];
        sW[i] = wor[i];
    }
    __syncthreads();

    const int r0 = (t >> 4) << 2;
    const int d0 = (t & 15) << 2;

    u64 acc[4][2];
#pragma unroll
    for (int i = 0; i < 4; i++) { acc[i][0] = 0ull; acc[i][1] = 0ull; }
    for (int bb = 0; bb < 64; bb++) {
        const float4 xa = *(const float4*)&sXT[bb * 68 + r0];
        const ulonglong2 w = *(const ulonglong2*)&sW[bb * 64 + d0];
        const u64 xp0 = pack2(xa.x, xa.x), xp1 = pack2(xa.y, xa.y);
        const u64 xp2 = pack2(xa.z, xa.z), xp3 = pack2(xa.w, xa.w);
        acc[0][0] = fma2(xp0, w.x, acc[0][0]); acc[0][1] = fma2(xp0, w.y, acc[0][1]);
        acc[1][0] = fma2(xp1, w.x, acc[1][0]); acc[1][1] = fma2(xp1, w.y, acc[1][1]);
        acc[2][0] = fma2(xp2, w.x, acc[2][0]); acc[2][1] = fma2(xp2, w.y, acc[2][1]);
        acc[3][0] = fma2(xp3, w.x, acc[3][0]); acc[3][1] = fma2(xp3, w.y, acc[3][1]);
    }
    __syncthreads();
#pragma unroll
    for (int i = 0; i < 4; i++)
        *(ulonglong2*)&sT[(r0 + i) * 64 + d0] = make_ulonglong2(acc[i][0], acc[i][1]);
    for (int i = t; i < 4096; i += 256) sW[i] = wol[i];
    __syncthreads();

#pragma unroll
    for (int i = 0; i < 4; i++) { acc[i][0] = 0ull; acc[i][1] = 0ull; }
    for (int a = 0; a < 64; a++) {
        const float4 la = *(const float4*)&sW[a * 64 + r0];
        const ulonglong2 td = *(const ulonglong2*)&sT[a * 64 + d0];
        const u64 lp0 = pack2(la.x, la.x), lp1 = pack2(la.y, la.y);
        const u64 lp2 = pack2(la.z, la.z), lp3 = pack2(la.w, la.w);
        acc[0][0] = fma2(lp0, td.x, acc[0][0]); acc[0][1] = fma2(lp0, td.y, acc[0][1]);
        acc[1][0] = fma2(lp1, td.x, acc[1][0]); acc[1][1] = fma2(lp1, td.y, acc[1][1]);
        acc[2][0] = fma2(lp2, td.x, acc[2][0]); acc[2][1] = fma2(lp2, td.y, acc[2][1]);
        acc[3][0] = fma2(lp3, td.x, acc[3][0]); acc[3][1] = fma2(lp3, td.y, acc[3][1]);
    }

#pragma unroll
    for (int i = 0; i < 4; i++) {
        const int c = r0 + i;
        const float4 bi = *(const float4*)&bo[c * 64 + d0];
        float v0, v1, v2, v3;
        unpack2(acc[i][0], v0, v1);
        unpack2(acc[i][1], v2, v3);
        float4 res = make_float4((v0 + bi.x) * 0.125f, (v1 + bi.y) * 0.125f,
                                 (v2 + bi.z) * 0.125f, (v3 + bi.w) * 0.125f);
        *(float4*)&dout[(size_t)token * 4096 + c * 64 + d0] = res;
    }
}

// ---------------------------------------------------------------------------
extern "C" void kernel_launch(void* const* d_in, const int* in_sizes, int n_in,
                              void* d_out, int out_size)
{
    const float* qin = (const float*)d_in[0];
    const float* kin = (const float*)d_in[1];
    const float* vin = (const float*)d_in[2];
    const float* wql = (const float*)d_in[3];
    const float* wqr = (const float*)d_in[4];
    const float* bq  = (const float*)d_in[5];
    const float* wkl = (const float*)d_in[6];
    const float* wkr = (const float*)d_in[7];
    const float* bk  = (const float*)d_in[8];
    const float* wvl = (const float*)d_in[9];
    const float* wvr = (const float*)d_in[10];
    const float* bv  = (const float*)d_in[11];
    const float* wol = (const float*)d_in[12];
    const float* wor = (const float*)d_in[13];
    const float* bo  = (const float*)d_in[14];
    float* dout = (float*)d_out;

    const int smem_attn = (8448 + 8192) * (int)sizeof(unsigned);  // 66560 B
    cudaFuncSetAttribute(attn_kernel, cudaFuncAttributeMaxDynamicSharedMemorySize, smem_attn);

    qkv_proj_kernel<<<dim3(256, 3), 256>>>(qin, kin, vin,
                                           wql, wqr, bq,
                                           wkl, wkr, bk,
                                           wvl, wvr, bv);
    attn_kernel<<<256, 256, smem_attn>>>();
    out_proj_kernel<<<256, 256>>>(wol, wor, bo, dout);
}